// round 2
// baseline (speedup 1.0000x reference)
#include <cuda_runtime.h>
#include <cmath>

#define EMB 64
#define NMAX 20000

// Scratch (device globals: no allocs allowed in kernel_launch)
__device__ float g_PHI[NMAX * 32];
__device__ float g_ENV[NMAX];

// ---------------------------------------------------------------------------
// Edge kernel: scatter env-weighted RBF vector + env into per-node sums.
// Recurrence trick: phi_{r+1}/phi_r = exp(2*beta*delta*(t - mid_r)); ratio of
// ratios is the constant q = exp(-2*beta*delta^2). Start at nearest center
// (the max) -> monotone decay both directions -> safe, ~4 exps per edge.
// ---------------------------------------------------------------------------
__global__ void edge_kernel(const float* __restrict__ dist,
                            const int* __restrict__ nb, int E,
                            float mu0, float delta, float inv_delta,
                            float beta, float c2, float q)
{
    int e = blockIdx.x * blockDim.x + threadIdx.x;
    if (e >= E) return;
    float d = dist[e];
    int j = nb[e];
    float env = 0.0f;
    if (d < 5.0f) env = 0.5f * (__cosf(0.62831853071795864769f * d) + 1.0f);
    atomicAdd(&g_ENV[j], env);

    float t = __expf(-d);
    int r0 = (int)floorf((t - mu0) * inv_delta + 0.5f);
    r0 = max(0, min(31, r0));
    float u0 = t - (mu0 + delta * (float)r0);
    float p0 = env * __expf(-beta * u0 * u0);
    float* phr = g_PHI + (size_t)j * 32;
    const float THR = 1e-12f;
    if (p0 > THR) atomicAdd(&phr[r0], p0);

    // upward sweep
    float w = __expf(c2 * (t - (mu0 + delta * ((float)r0 + 0.5f))));
    float p = p0;
    for (int r = r0 + 1; r < 32; ++r) {
        p *= w; w *= q;
        if (p <= THR) break;
        atomicAdd(&phr[r], p);
    }
    // downward sweep
    w = __expf(-c2 * (t - (mu0 + delta * ((float)r0 - 0.5f))));
    p = p0;
    for (int r = r0 - 1; r >= 0; --r) {
        p *= w; w *= q;
        if (p <= THR) break;
        atomicAdd(&phr[r], p);
    }
}

// ---------------------------------------------------------------------------
// Node kernel helpers: I/A/S decomposition of a 3x3, and reconstruction.
// comps layout: [iso, a01, a02, a12, s00, s01, s02, s11, s12]  (s22 = -s00-s11)
// ---------------------------------------------------------------------------
__device__ __forceinline__ void decomp9(const float x[9], float* iso,
                                        float a[3], float s[5])
{
    float m = (x[0] + x[4] + x[8]) * (1.0f / 3.0f);
    *iso = m;
    a[0] = 0.5f * (x[1] - x[3]);
    a[1] = 0.5f * (x[2] - x[6]);
    a[2] = 0.5f * (x[5] - x[7]);
    s[0] = x[0] - m;
    s[1] = 0.5f * (x[1] + x[3]);
    s[2] = 0.5f * (x[2] + x[6]);
    s[3] = x[4] - m;
    s[4] = 0.5f * (x[5] + x[7]);
}

__device__ __forceinline__ void build9(float iso, const float a[3],
                                       const float s[5], float Y[9])
{
    Y[0] = iso + s[0];        Y[1] = a[0] + s[1];       Y[2] = a[1] + s[2];
    Y[3] = s[1] - a[0];       Y[4] = iso + s[3];        Y[5] = a[2] + s[4];
    Y[6] = s[2] - a[1];       Y[7] = s[4] - a[2];       Y[8] = iso - s[0] - s[3];
}

// ---------------------------------------------------------------------------
// Node kernel: one warp per node; lane owns channels (lane, lane+32).
// Fully fused: normalize -> decompose -> coeff GEMV -> pre-mix -> sandwich
// Z=YM+MY -> norm -> decompose -> post-mix -> Y+Y@Y -> coalesced store.
// ---------------------------------------------------------------------------
__global__ void node_kernel(const float* __restrict__ X,
    const float* __restrict__ WIa, const float* __restrict__ WAa, const float* __restrict__ WSa,
    const float* __restrict__ WIb, const float* __restrict__ WAb, const float* __restrict__ WSb,
    const float* __restrict__ Wd, const float* __restrict__ bd,
    float* __restrict__ out, int N)
{
    __shared__ float xs[8][576];        // X staging / output staging
    __shared__ float comp[8][64][9];    // per-channel I/A/S components
    __shared__ float phis[8][32];       // per-node RBF sums

    int warp = threadIdx.x >> 5;
    int lane = threadIdx.x & 31;
    int n = blockIdx.x * 8 + warp;
    if (n >= N) return;

    // ---- stage X (coalesced float4) + phi ----
    {
        const float4* src = (const float4*)(X + (size_t)n * 576);
        float4* dst = (float4*)(&xs[warp][0]);
        #pragma unroll
        for (int i = 0; i < 5; ++i) {
            int idx = lane + 32 * i;
            if (idx < 144) dst[idx] = src[idx];
        }
        phis[warp][lane] = g_PHI[(size_t)n * 32 + lane];
    }
    float env = g_ENV[n];
    __syncwarp();

    // ---- per-channel normalize + decompose ----
    float ciso[2], ca[2][3], cs[2][5];
    #pragma unroll
    for (int h = 0; h < 2; ++h) {
        int c = lane + 32 * h;
        float x[9];
        #pragma unroll
        for (int k = 0; k < 9; ++k) x[k] = xs[warp][c * 9 + k];
        float f = 0.0f;
        #pragma unroll
        for (int k = 0; k < 9; ++k) f += x[k] * x[k];
        float sc = __fdividef(1.0f, f + 1.0f);
        #pragma unroll
        for (int k = 0; k < 9; ++k) x[k] *= sc;
        decomp9(x, &ciso[h], ca[h], cs[h]);
        float* cm = &comp[warp][c][0];
        cm[0] = ciso[h];
        cm[1] = ca[h][0]; cm[2] = ca[h][1]; cm[3] = ca[h][2];
        cm[4] = cs[h][0]; cm[5] = cs[h][1]; cm[6] = cs[h][2];
        cm[7] = cs[h][3]; cm[8] = cs[h][4];
    }
    __syncwarp();

    // ---- coefficient GEMV: F_g[c] = Wd[g*64+c,:] @ phi + env*bd[g*64+c] ----
    float fI[2], fA[2], fS[2];
    #pragma unroll
    for (int h = 0; h < 2; ++h) {
        int c = lane + 32 * h;
        float aI = env * bd[c];
        float aA = env * bd[64 + c];
        float aS = env * bd[128 + c];
        const float* wI = Wd + (size_t)c * 32;
        const float* wA = Wd + (size_t)(64 + c) * 32;
        const float* wS = Wd + (size_t)(128 + c) * 32;
        #pragma unroll 8
        for (int r = 0; r < 32; ++r) {
            float p = phis[warp][r];
            aI += wI[r] * p;
            aA += wA[r] * p;
            aS += wS[r] * p;
        }
        fI[h] = aI; fA[h] = aA; fS[h] = aS;
    }

    // ---- pre channel-mix (component form; sectors mix independently) ----
    float yi[2] = {0.f, 0.f};
    float ya[2][3] = {{0,0,0},{0,0,0}};
    float ys[2][5] = {{0,0,0,0,0},{0,0,0,0,0}};
    {
        int o0 = lane, o1 = lane + 32;
        #pragma unroll 4
        for (int c = 0; c < 64; ++c) {
            float m0 = comp[warp][c][0];
            float m1 = comp[warp][c][1], m2 = comp[warp][c][2], m3 = comp[warp][c][3];
            float m4 = comp[warp][c][4], m5 = comp[warp][c][5], m6 = comp[warp][c][6];
            float m7 = comp[warp][c][7], m8 = comp[warp][c][8];
            float w0 = WIa[o0 * 64 + c], w1 = WAa[o0 * 64 + c], w2 = WSa[o0 * 64 + c];
            yi[0] += w0 * m0;
            ya[0][0] += w1 * m1; ya[0][1] += w1 * m2; ya[0][2] += w1 * m3;
            ys[0][0] += w2 * m4; ys[0][1] += w2 * m5; ys[0][2] += w2 * m6;
            ys[0][3] += w2 * m7; ys[0][4] += w2 * m8;
            w0 = WIa[o1 * 64 + c]; w1 = WAa[o1 * 64 + c]; w2 = WSa[o1 * 64 + c];
            yi[1] += w0 * m0;
            ya[1][0] += w1 * m1; ya[1][1] += w1 * m2; ya[1][2] += w1 * m3;
            ys[1][0] += w2 * m4; ys[1][1] += w2 * m5; ys[1][2] += w2 * m6;
            ys[1][3] += w2 * m7; ys[1][4] += w2 * m8;
        }
    }

    // ---- Z = Y@M + M@Y, normalize, decompose ----
    float z2i[2], z2a[2][3], z2s[2][5];
    #pragma unroll
    for (int h = 0; h < 2; ++h) {
        float Y[9], M[9];
        build9(yi[h], ya[h], ys[h], Y);
        float mi = fI[h] * ciso[h];
        float A[3] = {fA[h] * ca[h][0], fA[h] * ca[h][1], fA[h] * ca[h][2]};
        float S[5] = {fS[h] * cs[h][0], fS[h] * cs[h][1], fS[h] * cs[h][2],
                      fS[h] * cs[h][3], fS[h] * cs[h][4]};
        build9(mi, A, S, M);
        float Z[9];
        #pragma unroll
        for (int i = 0; i < 3; ++i) {
            #pragma unroll
            for (int j = 0; j < 3; ++j) {
                float acc = 0.0f;
                #pragma unroll
                for (int k = 0; k < 3; ++k)
                    acc += Y[i * 3 + k] * M[k * 3 + j] + M[i * 3 + k] * Y[k * 3 + j];
                Z[i * 3 + j] = acc;
            }
        }
        float nrm = 0.0f;
        #pragma unroll
        for (int k = 0; k < 9; ++k) { float v = Z[k] + 1.0f; nrm += v * v; }
        float inv = __fdividef(1.0f, nrm);
        #pragma unroll
        for (int k = 0; k < 9; ++k) Z[k] *= inv;
        decomp9(Z, &z2i[h], z2a[h], z2s[h]);
    }
    __syncwarp();   // everyone done READING comp before overwrite
    #pragma unroll
    for (int h = 0; h < 2; ++h) {
        int c = lane + 32 * h;
        float* cm = &comp[warp][c][0];
        cm[0] = z2i[h];
        cm[1] = z2a[h][0]; cm[2] = z2a[h][1]; cm[3] = z2a[h][2];
        cm[4] = z2s[h][0]; cm[5] = z2s[h][1]; cm[6] = z2s[h][2];
        cm[7] = z2s[h][3]; cm[8] = z2s[h][4];
    }
    __syncwarp();

    // ---- post channel-mix ----
    float pi[2] = {0.f, 0.f};
    float pa[2][3] = {{0,0,0},{0,0,0}};
    float ps[2][5] = {{0,0,0,0,0},{0,0,0,0,0}};
    {
        int o0 = lane, o1 = lane + 32;
        #pragma unroll 4
        for (int c = 0; c < 64; ++c) {
            float m0 = comp[warp][c][0];
            float m1 = comp[warp][c][1], m2 = comp[warp][c][2], m3 = comp[warp][c][3];
            float m4 = comp[warp][c][4], m5 = comp[warp][c][5], m6 = comp[warp][c][6];
            float m7 = comp[warp][c][7], m8 = comp[warp][c][8];
            float w0 = WIb[o0 * 64 + c], w1 = WAb[o0 * 64 + c], w2 = WSb[o0 * 64 + c];
            pi[0] += w0 * m0;
            pa[0][0] += w1 * m1; pa[0][1] += w1 * m2; pa[0][2] += w1 * m3;
            ps[0][0] += w2 * m4; ps[0][1] += w2 * m5; ps[0][2] += w2 * m6;
            ps[0][3] += w2 * m7; ps[0][4] += w2 * m8;
            w0 = WIb[o1 * 64 + c]; w1 = WAb[o1 * 64 + c]; w2 = WSb[o1 * 64 + c];
            pi[1] += w0 * m0;
            pa[1][0] += w1 * m1; pa[1][1] += w1 * m2; pa[1][2] += w1 * m3;
            ps[1][0] += w2 * m4; ps[1][1] += w2 * m5; ps[1][2] += w2 * m6;
            ps[1][3] += w2 * m7; ps[1][4] += w2 * m8;
        }
    }

    // ---- out = Y2 + Y2@Y2, stage and store coalesced ----
    #pragma unroll
    for (int h = 0; h < 2; ++h) {
        int c = lane + 32 * h;
        float Y2[9];
        build9(pi[h], pa[h], ps[h], Y2);
        float* od = &xs[warp][c * 9];
        #pragma unroll
        for (int i = 0; i < 3; ++i) {
            #pragma unroll
            for (int j = 0; j < 3; ++j) {
                float acc = Y2[i * 3 + j];
                #pragma unroll
                for (int k = 0; k < 3; ++k)
                    acc += Y2[i * 3 + k] * Y2[k * 3 + j];
                od[i * 3 + j] = acc;
            }
        }
    }
    __syncwarp();
    {
        float4* dst = (float4*)(out + (size_t)n * 576);
        const float4* src = (const float4*)(&xs[warp][0]);
        #pragma unroll
        for (int i = 0; i < 5; ++i) {
            int idx = lane + 32 * i;
            if (idx < 144) dst[idx] = src[idx];
        }
    }
}

// ---------------------------------------------------------------------------
extern "C" void kernel_launch(void* const* d_in, const int* in_sizes, int n_in,
                              void* d_out, int out_size)
{
    const float* X    = (const float*)d_in[0];
    const float* dist = (const float*)d_in[1];
    const int*   nb   = (const int*)d_in[2];
    const float* WIa  = (const float*)d_in[3];
    const float* WAa  = (const float*)d_in[4];
    const float* WSa  = (const float*)d_in[5];
    const float* WIb  = (const float*)d_in[6];
    const float* WAb  = (const float*)d_in[7];
    const float* WSb  = (const float*)d_in[8];
    const float* Wd   = (const float*)d_in[9];
    const float* bd   = (const float*)d_in[10];
    float* out = (float*)d_out;

    int N = in_sizes[0] / 576;
    int E = in_sizes[1];

    void* phi_ptr = nullptr;
    void* env_ptr = nullptr;
    cudaGetSymbolAddress(&phi_ptr, g_PHI);
    cudaGetSymbolAddress(&env_ptr, g_ENV);
    cudaMemsetAsync(phi_ptr, 0, sizeof(float) * (size_t)N * 32, 0);
    cudaMemsetAsync(env_ptr, 0, sizeof(float) * (size_t)N, 0);

    double e5    = exp(-5.0);
    double delta = (1.0 - e5) / 31.0;
    double bb    = (2.0 / 32.0) * (1.0 - e5);
    double beta  = 1.0 / (bb * bb);
    float  c2    = (float)(2.0 * beta * delta);
    float  qf    = (float)exp(-2.0 * beta * delta * delta);

    edge_kernel<<<(E + 255) / 256, 256>>>(dist, nb, E,
        (float)e5, (float)delta, (float)(1.0 / delta), (float)beta, c2, qf);
    node_kernel<<<(N + 7) / 8, 256>>>(X, WIa, WAa, WSa, WIb, WAb, WSb,
                                      Wd, bd, out, N);
}

// round 3
// speedup vs baseline: 12.5004x; 12.5004x over previous
#include <cuda_runtime.h>
#include <cmath>

#define NMAX 20000

// Scratch (device globals: no allocs allowed in kernel_launch)
__device__ float g_PHI[NMAX * 32];
__device__ float g_ENV[NMAX];

// ---------------------------------------------------------------------------
// Edge kernel: scatter env-weighted RBF vector + env into per-node sums.
// Recurrence: phi_{r+1}/phi_r ratio-of-ratios is constant q; start at nearest
// center (max) -> monotone decay both directions, ~4 exps per edge.
// ---------------------------------------------------------------------------
__global__ void edge_kernel(const float* __restrict__ dist,
                            const int* __restrict__ nb, int E,
                            float mu0, float delta, float inv_delta,
                            float beta, float c2, float q)
{
    int e = blockIdx.x * blockDim.x + threadIdx.x;
    if (e >= E) return;
    float d = dist[e];
    int j = nb[e];
    float env = 0.0f;
    if (d < 5.0f) env = 0.5f * (__cosf(0.62831853071795864769f * d) + 1.0f);
    atomicAdd(&g_ENV[j], env);

    float t = __expf(-d);
    int r0 = (int)floorf((t - mu0) * inv_delta + 0.5f);
    r0 = max(0, min(31, r0));
    float u0 = t - (mu0 + delta * (float)r0);
    float p0 = env * __expf(-beta * u0 * u0);
    float* phr = g_PHI + (size_t)j * 32;
    const float THR = 1e-12f;
    if (p0 > THR) atomicAdd(&phr[r0], p0);

    float w = __expf(c2 * (t - (mu0 + delta * ((float)r0 + 0.5f))));
    float p = p0;
    for (int r = r0 + 1; r < 32; ++r) {
        p *= w; w *= q;
        if (p <= THR) break;
        atomicAdd(&phr[r], p);
    }
    w = __expf(-c2 * (t - (mu0 + delta * ((float)r0 - 0.5f))));
    p = p0;
    for (int r = r0 - 1; r >= 0; --r) {
        p *= w; w *= q;
        if (p <= THR) break;
        atomicAdd(&phr[r], p);
    }
}

// ---------------------------------------------------------------------------
// f32x2 packed FMA helpers (sm_103a FFMA2 via PTX)
// ---------------------------------------------------------------------------
__device__ __forceinline__ void ffma2(unsigned long long& d,
                                      unsigned long long a,
                                      unsigned long long b)
{
    asm("fma.rn.f32x2 %0, %1, %2, %0;" : "+l"(d) : "l"(a), "l"(b));
}
__device__ __forceinline__ float sum2(unsigned long long v)
{
    float lo, hi;
    asm("mov.b64 {%0, %1}, %2;" : "=f"(lo), "=f"(hi) : "l"(v));
    return lo + hi;
}

__device__ __forceinline__ void decomp9(const float x[9], float* iso,
                                        float a[3], float s[5])
{
    float m = (x[0] + x[4] + x[8]) * (1.0f / 3.0f);
    *iso = m;
    a[0] = 0.5f * (x[1] - x[3]);
    a[1] = 0.5f * (x[2] - x[6]);
    a[2] = 0.5f * (x[5] - x[7]);
    s[0] = x[0] - m;
    s[1] = 0.5f * (x[1] + x[3]);
    s[2] = 0.5f * (x[2] + x[6]);
    s[3] = x[4] - m;
    s[4] = 0.5f * (x[5] + x[7]);
}

__device__ __forceinline__ void build9(float iso, const float a[3],
                                       const float s[5], float Y[9])
{
    Y[0] = iso + s[0];        Y[1] = a[0] + s[1];       Y[2] = a[1] + s[2];
    Y[3] = s[1] - a[0];       Y[4] = iso + s[3];        Y[5] = a[2] + s[4];
    Y[6] = s[2] - a[1];       Y[7] = s[4] - a[2];       Y[8] = iso - s[0] - s[3];
}

// ---------------------------------------------------------------------------
// Shared-memory layout (floats), one block = 16 warps = 16 nodes per iter
// ---------------------------------------------------------------------------
#define NW 16
#define WROW 66                    // padded weight row (conflict-free LDS.64)
#define OFF_W    0                 // 6 * 64 * 66 = 25344
#define OFF_WD   25344             // WdT[32][192]  = 6144
#define OFF_COMP 31488             // per warp: 32 rows * 20 floats = 640
#define OFF_XS   41728             // per warp: 576
#define OFF_PHI  50944             // per warp: 33
#define SMEM_FLOATS 51472          // = 205,888 bytes

// mix: out components over 64 channels, c-pair packed f32x2.
// cbase rows: [j=c/2][2k + (c&1)], row stride 20 floats.
__device__ __forceinline__ void mix64(const float* __restrict__ WI,
                                      const float* __restrict__ WA,
                                      const float* __restrict__ WS,
                                      const float* __restrict__ cbase,
                                      int lane,
                                      float yi[2], float ya[2][3], float ys[2][5])
{
    unsigned long long aI[2] = {0ull, 0ull};
    unsigned long long aA[2][3] = {{0,0,0},{0,0,0}};
    unsigned long long aS[2][5] = {{0,0,0,0,0},{0,0,0,0,0}};
    const float* wI0 = WI + lane * WROW;
    const float* wI1 = WI + (lane + 32) * WROW;
    const float* wA0 = WA + lane * WROW;
    const float* wA1 = WA + (lane + 32) * WROW;
    const float* wS0 = WS + lane * WROW;
    const float* wS1 = WS + (lane + 32) * WROW;

    #pragma unroll 8
    for (int j = 0; j < 32; ++j) {
        const float* mrow = cbase + j * 20;
        ulonglong2 q0 = *(const ulonglong2*)(mrow);       // m0 m1
        ulonglong2 q1 = *(const ulonglong2*)(mrow + 4);   // m2 m3
        ulonglong2 q2 = *(const ulonglong2*)(mrow + 8);   // m4 m5
        ulonglong2 q3 = *(const ulonglong2*)(mrow + 12);  // m6 m7
        unsigned long long m8 = *(const unsigned long long*)(mrow + 16);

        unsigned long long w;
        w = *(const unsigned long long*)(wI0 + 2 * j);
        ffma2(aI[0], w, q0.x);
        w = *(const unsigned long long*)(wI1 + 2 * j);
        ffma2(aI[1], w, q0.x);
        w = *(const unsigned long long*)(wA0 + 2 * j);
        ffma2(aA[0][0], w, q0.y); ffma2(aA[0][1], w, q1.x); ffma2(aA[0][2], w, q1.y);
        w = *(const unsigned long long*)(wA1 + 2 * j);
        ffma2(aA[1][0], w, q0.y); ffma2(aA[1][1], w, q1.x); ffma2(aA[1][2], w, q1.y);
        w = *(const unsigned long long*)(wS0 + 2 * j);
        ffma2(aS[0][0], w, q2.x); ffma2(aS[0][1], w, q2.y);
        ffma2(aS[0][2], w, q3.x); ffma2(aS[0][3], w, q3.y);
        ffma2(aS[0][4], w, m8);
        w = *(const unsigned long long*)(wS1 + 2 * j);
        ffma2(aS[1][0], w, q2.x); ffma2(aS[1][1], w, q2.y);
        ffma2(aS[1][2], w, q3.x); ffma2(aS[1][3], w, q3.y);
        ffma2(aS[1][4], w, m8);
    }
    #pragma unroll
    for (int h = 0; h < 2; ++h) {
        yi[h] = sum2(aI[h]);
        #pragma unroll
        for (int k = 0; k < 3; ++k) ya[h][k] = sum2(aA[h][k]);
        #pragma unroll
        for (int k = 0; k < 5; ++k) ys[h][k] = sum2(aS[h][k]);
    }
}

__global__ __launch_bounds__(512, 1)
void node_kernel(const float* __restrict__ X,
    const float* __restrict__ WIa, const float* __restrict__ WAa, const float* __restrict__ WSa,
    const float* __restrict__ WIb, const float* __restrict__ WAb, const float* __restrict__ WSb,
    const float* __restrict__ Wd, const float* __restrict__ bd,
    float* __restrict__ out, int N, int nstep)
{
    extern __shared__ float sm[];
    int tid  = threadIdx.x;
    int warp = tid >> 5;
    int lane = tid & 31;

    // ---- stage weights (once per block) ----
    {
        const float* Ws[6] = {WIa, WAa, WSa, WIb, WAb, WSb};
        #pragma unroll
        for (int m = 0; m < 6; ++m) {
            const float* src = Ws[m];
            float* dst = sm + OFF_W + m * (64 * WROW);
            for (int idx = tid; idx < 4096; idx += 512)
                dst[(idx >> 6) * WROW + (idx & 63)] = src[idx];
        }
        for (int idx = tid; idx < 6144; idx += 512) {
            int gc = idx >> 5, r = idx & 31;
            sm[OFF_WD + r * 192 + gc] = Wd[idx];
        }
    }
    __syncthreads();

    float* xs   = sm + OFF_XS   + warp * 576;
    float* cp   = sm + OFF_COMP + warp * 640;
    float* phis = sm + OFF_PHI  + warp * 33;

    for (int n = blockIdx.x * NW + warp; n < N; n += nstep) {
        // ---- stage X (coalesced float4) + phi ----
        {
            const float4* src = (const float4*)(X + (size_t)n * 576);
            float4* dst = (float4*)xs;
            #pragma unroll
            for (int i = 0; i < 5; ++i) {
                int idx = lane + 32 * i;
                if (idx < 144) dst[idx] = src[idx];
            }
            phis[lane] = g_PHI[(size_t)n * 32 + lane];
        }
        float env = g_ENV[n];
        __syncwarp();

        // ---- per-channel normalize + decompose; write packed comp rows ----
        float ciso[2], ca[2][3], cs[2][5];
        #pragma unroll
        for (int h = 0; h < 2; ++h) {
            int c = lane + 32 * h;
            float x[9];
            #pragma unroll
            for (int k = 0; k < 9; ++k) x[k] = xs[c * 9 + k];
            float f = 0.0f;
            #pragma unroll
            for (int k = 0; k < 9; ++k) f += x[k] * x[k];
            float sc = __fdividef(1.0f, f + 1.0f);
            #pragma unroll
            for (int k = 0; k < 9; ++k) x[k] *= sc;
            decomp9(x, &ciso[h], ca[h], cs[h]);
            float* row = cp + (c >> 1) * 20 + (c & 1);
            row[0]  = ciso[h];
            row[2]  = ca[h][0]; row[4]  = ca[h][1]; row[6]  = ca[h][2];
            row[8]  = cs[h][0]; row[10] = cs[h][1]; row[12] = cs[h][2];
            row[14] = cs[h][3]; row[16] = cs[h][4];
        }
        __syncwarp();

        // ---- coefficient GEMV: F_g[c] = WdT[:,g*64+c] . phi + env*bd ----
        float fI[2], fA[2], fS[2];
        #pragma unroll
        for (int h = 0; h < 2; ++h) {
            int c = lane + 32 * h;
            float aI = env * bd[c];
            float aA = env * bd[64 + c];
            float aS = env * bd[128 + c];
            #pragma unroll 8
            for (int r = 0; r < 32; ++r) {
                float p = phis[r];
                const float* wr = sm + OFF_WD + r * 192;
                aI += wr[c] * p;
                aA += wr[64 + c] * p;
                aS += wr[128 + c] * p;
            }
            fI[h] = aI; fA[h] = aA; fS[h] = aS;
        }

        // ---- pre channel-mix ----
        float yi[2], ya[2][3], ys[2][5];
        mix64(sm + OFF_W + 0 * (64 * WROW), sm + OFF_W + 1 * (64 * WROW),
              sm + OFF_W + 2 * (64 * WROW), cp, lane, yi, ya, ys);

        // ---- Z = Y@M + M@Y, normalize, decompose ----
        float z2i[2], z2a[2][3], z2s[2][5];
        #pragma unroll
        for (int h = 0; h < 2; ++h) {
            float Y[9], M[9];
            build9(yi[h], ya[h], ys[h], Y);
            float mi = fI[h] * ciso[h];
            float A[3] = {fA[h] * ca[h][0], fA[h] * ca[h][1], fA[h] * ca[h][2]};
            float S[5] = {fS[h] * cs[h][0], fS[h] * cs[h][1], fS[h] * cs[h][2],
                          fS[h] * cs[h][3], fS[h] * cs[h][4]};
            build9(mi, A, S, M);
            float Z[9];
            #pragma unroll
            for (int i = 0; i < 3; ++i)
                #pragma unroll
                for (int jj = 0; jj < 3; ++jj) {
                    float acc = 0.0f;
                    #pragma unroll
                    for (int k = 0; k < 3; ++k)
                        acc += Y[i * 3 + k] * M[k * 3 + jj] + M[i * 3 + k] * Y[k * 3 + jj];
                    Z[i * 3 + jj] = acc;
                }
            float nrm = 0.0f;
            #pragma unroll
            for (int k = 0; k < 9; ++k) { float v = Z[k] + 1.0f; nrm += v * v; }
            float inv = __fdividef(1.0f, nrm);
            #pragma unroll
            for (int k = 0; k < 9; ++k) Z[k] *= inv;
            decomp9(Z, &z2i[h], z2a[h], z2s[h]);
        }
        __syncwarp();   // all lanes done reading comp before overwrite
        #pragma unroll
        for (int h = 0; h < 2; ++h) {
            int c = lane + 32 * h;
            float* row = cp + (c >> 1) * 20 + (c & 1);
            row[0]  = z2i[h];
            row[2]  = z2a[h][0]; row[4]  = z2a[h][1]; row[6]  = z2a[h][2];
            row[8]  = z2s[h][0]; row[10] = z2s[h][1]; row[12] = z2s[h][2];
            row[14] = z2s[h][3]; row[16] = z2s[h][4];
        }
        __syncwarp();

        // ---- post channel-mix ----
        float pi[2], pa[2][3], ps[2][5];
        mix64(sm + OFF_W + 3 * (64 * WROW), sm + OFF_W + 4 * (64 * WROW),
              sm + OFF_W + 5 * (64 * WROW), cp, lane, pi, pa, ps);

        // ---- out = Y2 + Y2@Y2, stage and store coalesced ----
        #pragma unroll
        for (int h = 0; h < 2; ++h) {
            int c = lane + 32 * h;
            float Y2[9];
            build9(pi[h], pa[h], ps[h], Y2);
            float* od = xs + c * 9;
            #pragma unroll
            for (int i = 0; i < 3; ++i)
                #pragma unroll
                for (int jj = 0; jj < 3; ++jj) {
                    float acc = Y2[i * 3 + jj];
                    #pragma unroll
                    for (int k = 0; k < 3; ++k)
                        acc += Y2[i * 3 + k] * Y2[k * 3 + jj];
                    od[i * 3 + jj] = acc;
                }
        }
        __syncwarp();
        {
            float4* dst = (float4*)(out + (size_t)n * 576);
            const float4* src = (const float4*)xs;
            #pragma unroll
            for (int i = 0; i < 5; ++i) {
                int idx = lane + 32 * i;
                if (idx < 144) dst[idx] = src[idx];
            }
        }
        __syncwarp();   // xs fully read before next iteration overwrites
    }
}

// ---------------------------------------------------------------------------
extern "C" void kernel_launch(void* const* d_in, const int* in_sizes, int n_in,
                              void* d_out, int out_size)
{
    const float* X    = (const float*)d_in[0];
    const float* dist = (const float*)d_in[1];
    const int*   nb   = (const int*)d_in[2];
    const float* WIa  = (const float*)d_in[3];
    const float* WAa  = (const float*)d_in[4];
    const float* WSa  = (const float*)d_in[5];
    const float* WIb  = (const float*)d_in[6];
    const float* WAb  = (const float*)d_in[7];
    const float* WSb  = (const float*)d_in[8];
    const float* Wd   = (const float*)d_in[9];
    const float* bd   = (const float*)d_in[10];
    float* out = (float*)d_out;

    int N = in_sizes[0] / 576;
    int E = in_sizes[1];

    void* phi_ptr = nullptr;
    void* env_ptr = nullptr;
    cudaGetSymbolAddress(&phi_ptr, g_PHI);
    cudaGetSymbolAddress(&env_ptr, g_ENV);
    cudaMemsetAsync(phi_ptr, 0, sizeof(float) * (size_t)N * 32, 0);
    cudaMemsetAsync(env_ptr, 0, sizeof(float) * (size_t)N, 0);

    double e5    = exp(-5.0);
    double delta = (1.0 - e5) / 31.0;
    double bb    = (2.0 / 32.0) * (1.0 - e5);
    double beta  = 1.0 / (bb * bb);
    float  c2    = (float)(2.0 * beta * delta);
    float  qf    = (float)exp(-2.0 * beta * delta * delta);

    edge_kernel<<<(E + 255) / 256, 256>>>(dist, nb, E,
        (float)e5, (float)delta, (float)(1.0 / delta), (float)beta, c2, qf);

    static int smem_set = 0;
    if (!smem_set) {
        cudaFuncSetAttribute(node_kernel,
                             cudaFuncAttributeMaxDynamicSharedMemorySize,
                             SMEM_FLOATS * sizeof(float));
        smem_set = 1;
    }
    int grid = 148;
    int nstep = grid * NW;
    node_kernel<<<grid, 512, SMEM_FLOATS * sizeof(float)>>>(
        X, WIa, WAa, WSa, WIb, WAb, WSb, Wd, bd, out, N, nstep);
}

// round 4
// speedup vs baseline: 14.5913x; 1.1673x over previous
#include <cuda_runtime.h>
#include <cmath>

#define NMAX 20000

__device__ float g_PHI[NMAX * 32];
__device__ float g_ENV[NMAX];

// ---------------------------------------------------------------------------
// Edge kernel: scatter env-weighted RBF vector + env into per-node sums.
// ---------------------------------------------------------------------------
__global__ void edge_kernel(const float* __restrict__ dist,
                            const int* __restrict__ nb, int E,
                            float mu0, float delta, float inv_delta,
                            float beta, float c2, float q)
{
    int e = blockIdx.x * blockDim.x + threadIdx.x;
    if (e >= E) return;
    float d = dist[e];
    int j = nb[e];
    float env = 0.0f;
    if (d < 5.0f) env = 0.5f * (__cosf(0.62831853071795864769f * d) + 1.0f);
    atomicAdd(&g_ENV[j], env);

    float t = __expf(-d);
    int r0 = (int)floorf((t - mu0) * inv_delta + 0.5f);
    r0 = max(0, min(31, r0));
    float u0 = t - (mu0 + delta * (float)r0);
    float p0 = env * __expf(-beta * u0 * u0);
    float* phr = g_PHI + (size_t)j * 32;
    const float THR = 1e-6f;
    if (p0 > THR) atomicAdd(&phr[r0], p0);

    float w = __expf(c2 * (t - (mu0 + delta * ((float)r0 + 0.5f))));
    float p = p0;
    for (int r = r0 + 1; r < 32; ++r) {
        p *= w; w *= q;
        if (p <= THR) break;
        atomicAdd(&phr[r], p);
    }
    w = __expf(-c2 * (t - (mu0 + delta * ((float)r0 - 0.5f))));
    p = p0;
    for (int r = r0 - 1; r >= 0; --r) {
        p *= w; w *= q;
        if (p <= THR) break;
        atomicAdd(&phr[r], p);
    }
}

// ---------------------------------------------------------------------------
// f32x2 packed FMA helpers
// ---------------------------------------------------------------------------
__device__ __forceinline__ void ffma2(unsigned long long& d,
                                      unsigned long long a,
                                      unsigned long long b)
{
    asm("fma.rn.f32x2 %0, %1, %2, %0;" : "+l"(d) : "l"(a), "l"(b));
}
__device__ __forceinline__ float sum2(unsigned long long v)
{
    float lo, hi;
    asm("mov.b64 {%0, %1}, %2;" : "=f"(lo), "=f"(hi) : "l"(v));
    return lo + hi;
}

__device__ __forceinline__ void decomp9(const float x[9], float* iso,
                                        float a[3], float s[5])
{
    float m = (x[0] + x[4] + x[8]) * (1.0f / 3.0f);
    *iso = m;
    a[0] = 0.5f * (x[1] - x[3]);
    a[1] = 0.5f * (x[2] - x[6]);
    a[2] = 0.5f * (x[5] - x[7]);
    s[0] = x[0] - m;
    s[1] = 0.5f * (x[1] + x[3]);
    s[2] = 0.5f * (x[2] + x[6]);
    s[3] = x[4] - m;
    s[4] = 0.5f * (x[5] + x[7]);
}

__device__ __forceinline__ void build9(float iso, const float a[3],
                                       const float s[5], float Y[9])
{
    Y[0] = iso + s[0];        Y[1] = a[0] + s[1];       Y[2] = a[1] + s[2];
    Y[3] = s[1] - a[0];       Y[4] = iso + s[3];        Y[5] = a[2] + s[4];
    Y[6] = s[2] - a[1];       Y[7] = s[4] - a[2];       Y[8] = iso - s[0] - s[3];
}

// ---------------------------------------------------------------------------
// Shared-memory layout (floats). 8 warps/block, 4 nodes/warp per iteration.
// Weight rows padded to 68 (LDS.128 16B-aligned, conflict-free banks 4l+4j).
// Comp planes: k=0..2 antisym, 3..7 traceless-sym, 8 iso; plane stride 68.
// ---------------------------------------------------------------------------
#define NWARP 8
#define WROW 68
#define PLANE 68
#define CPSZ (9 * PLANE)          // 612 per node
#define OFF_W    0                // 6 * 64 * 68 = 26112
#define OFF_WDT  26112            // WdT[32][192] = 6144
#define OFF_WARP 32256
#define WSZ      3160             // cp 4*612=2448 | xs 576 | phi 4*33=132 | pad
#define SMEM_FLOATS (OFF_WARP + NWARP * WSZ)   // 57,536 floats = 230,144 B

// One sector pass: NC comps starting at plane k0, accumulate 4 nodes.
template<int NC>
__device__ __forceinline__ void sector_pass(const float* __restrict__ Wsec,
                                            const float* __restrict__ cp,
                                            int lane,
                                            unsigned long long acc[NC][2][4])
{
    const float* w0 = Wsec + lane * WROW;
    const float* w1 = Wsec + (lane + 32) * WROW;
    #pragma unroll 4
    for (int j = 0; j < 16; ++j) {
        ulonglong2 wv0 = *(const ulonglong2*)(w0 + 4 * j);
        ulonglong2 wv1 = *(const ulonglong2*)(w1 + 4 * j);
        #pragma unroll
        for (int n = 0; n < 4; ++n) {
            const float* base = cp + n * CPSZ + 4 * j;
            #pragma unroll
            for (int k = 0; k < NC; ++k) {
                ulonglong2 m = *(const ulonglong2*)(base + k * PLANE);
                ffma2(acc[k][0][n], wv0.x, m.x);
                ffma2(acc[k][0][n], wv0.y, m.y);
                ffma2(acc[k][1][n], wv1.x, m.x);
                ffma2(acc[k][1][n], wv1.y, m.y);
            }
        }
    }
}

__global__ __launch_bounds__(256, 1)
void node_kernel(const float* __restrict__ X,
    const float* __restrict__ WIa, const float* __restrict__ WAa, const float* __restrict__ WSa,
    const float* __restrict__ WIb, const float* __restrict__ WAb, const float* __restrict__ WSb,
    const float* __restrict__ Wd, const float* __restrict__ bd,
    float* __restrict__ out, int N)
{
    extern __shared__ float sm[];
    int tid  = threadIdx.x;
    int warp = tid >> 5;
    int lane = tid & 31;

    // ---- stage weights (once per block) ----
    {
        const float* Ws[6] = {WAa, WSa, WIa, WAb, WSb, WIb};   // A,S,I order
        #pragma unroll
        for (int m = 0; m < 6; ++m) {
            const float* src = Ws[m];
            float* dst = sm + OFF_W + m * (64 * WROW);
            for (int idx = tid; idx < 4096; idx += 256)
                dst[(idx >> 6) * WROW + (idx & 63)] = src[idx];
        }
        for (int idx = tid; idx < 6144; idx += 256) {
            int gc = idx >> 5, r = idx & 31;
            sm[OFF_WDT + r * 192 + gc] = Wd[idx];
        }
    }
    // bias hoist (constant over nodes)
    float bI0 = bd[lane],        bI1 = bd[lane + 32];
    float bA0 = bd[64 + lane],   bA1 = bd[96 + lane];
    float bS0 = bd[128 + lane],  bS1 = bd[160 + lane];
    __syncthreads();

    float* cp   = sm + OFF_WARP + warp * WSZ;        // 4 * 612
    float* xs   = cp + 4 * CPSZ;                      // 576
    float* phis = xs + 576;                           // 4 * 33

    const float* smWA_a = sm + OFF_W + 0 * (64 * WROW);
    const float* smWS_a = sm + OFF_W + 1 * (64 * WROW);
    const float* smWI_a = sm + OFF_W + 2 * (64 * WROW);
    const float* smWA_b = sm + OFF_W + 3 * (64 * WROW);
    const float* smWS_b = sm + OFF_W + 4 * (64 * WROW);
    const float* smWI_b = sm + OFF_W + 5 * (64 * WROW);
    const float* smWdT  = sm + OFF_WDT;

    int Q = (N + 3) >> 2;
    int gw = blockIdx.x * NWARP + warp;
    int step = gridDim.x * NWARP;

    for (int q = gw; q < Q; q += step) {
        int n0 = q << 2;

        // ---- stage phi + env ----
        float env[4];
        #pragma unroll
        for (int n = 0; n < 4; ++n) {
            int node = n0 + n;
            bool v = node < N;
            phis[n * 33 + lane] = v ? g_PHI[(size_t)node * 32 + lane] : 0.0f;
            env[n] = v ? g_ENV[node] : 0.0f;
        }
        __syncwarp();

        // ---- per-node: stage X, normalize, decompose -> comp planes ----
        #pragma unroll
        for (int n = 0; n < 4; ++n) {
            int node = n0 + n;
            if (node < N) {
                const float4* src = (const float4*)(X + (size_t)node * 576);
                float4* dst = (float4*)xs;
                #pragma unroll
                for (int i = 0; i < 5; ++i) {
                    int idx = lane + 32 * i;
                    if (idx < 144) dst[idx] = src[idx];
                }
            }
            __syncwarp();
            float* cpn = cp + n * CPSZ;
            #pragma unroll
            for (int h = 0; h < 2; ++h) {
                int c = lane + 32 * h;
                float x[9];
                #pragma unroll
                for (int k = 0; k < 9; ++k) x[k] = xs[c * 9 + k];
                float f = 0.0f;
                #pragma unroll
                for (int k = 0; k < 9; ++k) f += x[k] * x[k];
                float sc = __fdividef(1.0f, f + 1.0f);
                #pragma unroll
                for (int k = 0; k < 9; ++k) x[k] *= sc;
                float iso, a[3], s[5];
                decomp9(x, &iso, a, s);
                cpn[0 * PLANE + c] = a[0];
                cpn[1 * PLANE + c] = a[1];
                cpn[2 * PLANE + c] = a[2];
                cpn[3 * PLANE + c] = s[0];
                cpn[4 * PLANE + c] = s[1];
                cpn[5 * PLANE + c] = s[2];
                cpn[6 * PLANE + c] = s[3];
                cpn[7 * PLANE + c] = s[4];
                cpn[8 * PLANE + c] = iso;
            }
            __syncwarp();
        }

        // ---- coefficient GEMV (weights shared across the 4 nodes) ----
        float fI[2][4], fA[2][4], fS[2][4];
        #pragma unroll
        for (int n = 0; n < 4; ++n) {
            fI[0][n] = env[n] * bI0; fI[1][n] = env[n] * bI1;
            fA[0][n] = env[n] * bA0; fA[1][n] = env[n] * bA1;
            fS[0][n] = env[n] * bS0; fS[1][n] = env[n] * bS1;
        }
        #pragma unroll 4
        for (int r = 0; r < 32; ++r) {
            const float* wr = smWdT + r * 192;
            float wi0 = wr[lane],       wi1 = wr[lane + 32];
            float wa0 = wr[64 + lane],  wa1 = wr[96 + lane];
            float ws0 = wr[128 + lane], ws1 = wr[160 + lane];
            #pragma unroll
            for (int n = 0; n < 4; ++n) {
                float p = phis[n * 33 + r];
                fI[0][n] += wi0 * p; fI[1][n] += wi1 * p;
                fA[0][n] += wa0 * p; fA[1][n] += wa1 * p;
                fS[0][n] += ws0 * p; fS[1][n] += ws1 * p;
            }
        }

        // ---- pre mixes (sector-split) ----
        float yi[2][4], ya[3][2][4], ys[5][2][4];
        {
            unsigned long long accA[3][2][4] = {};
            sector_pass<3>(smWA_a, cp, lane, accA);
            #pragma unroll
            for (int k = 0; k < 3; ++k)
                #pragma unroll
                for (int h = 0; h < 2; ++h)
                    #pragma unroll
                    for (int n = 0; n < 4; ++n) ya[k][h][n] = sum2(accA[k][h][n]);
        }
        {
            unsigned long long accS[5][2][4] = {};
            sector_pass<5>(smWS_a, cp + 3 * PLANE, lane, accS);
            #pragma unroll
            for (int k = 0; k < 5; ++k)
                #pragma unroll
                for (int h = 0; h < 2; ++h)
                    #pragma unroll
                    for (int n = 0; n < 4; ++n) ys[k][h][n] = sum2(accS[k][h][n]);
        }
        {
            unsigned long long accI[1][2][4] = {};
            sector_pass<1>(smWI_a, cp + 8 * PLANE, lane, accI);
            #pragma unroll
            for (int h = 0; h < 2; ++h)
                #pragma unroll
                for (int n = 0; n < 4; ++n) yi[h][n] = sum2(accI[0][h][n]);
        }
        __syncwarp();

        // ---- sandwich: Z = YM + MY, normalize, decompose -> overwrite comps
        #pragma unroll
        for (int n = 0; n < 4; ++n) {
            float* cpn = cp + n * CPSZ;
            #pragma unroll
            for (int h = 0; h < 2; ++h) {
                int c = lane + 32 * h;
                float Y[9], M[9];
                float av[3] = {ya[0][h][n], ya[1][h][n], ya[2][h][n]};
                float sv[5] = {ys[0][h][n], ys[1][h][n], ys[2][h][n],
                               ys[3][h][n], ys[4][h][n]};
                build9(yi[h][n], av, sv, Y);
                float mi = fI[h][n] * cpn[8 * PLANE + c];
                float A[3] = {fA[h][n] * cpn[0 * PLANE + c],
                              fA[h][n] * cpn[1 * PLANE + c],
                              fA[h][n] * cpn[2 * PLANE + c]};
                float S[5] = {fS[h][n] * cpn[3 * PLANE + c],
                              fS[h][n] * cpn[4 * PLANE + c],
                              fS[h][n] * cpn[5 * PLANE + c],
                              fS[h][n] * cpn[6 * PLANE + c],
                              fS[h][n] * cpn[7 * PLANE + c]};
                build9(mi, A, S, M);
                float Z[9];
                #pragma unroll
                for (int i = 0; i < 3; ++i)
                    #pragma unroll
                    for (int jj = 0; jj < 3; ++jj) {
                        float acc = 0.0f;
                        #pragma unroll
                        for (int k = 0; k < 3; ++k)
                            acc += Y[i * 3 + k] * M[k * 3 + jj]
                                 + M[i * 3 + k] * Y[k * 3 + jj];
                        Z[i * 3 + jj] = acc;
                    }
                float nrm = 0.0f;
                #pragma unroll
                for (int k = 0; k < 9; ++k) { float v = Z[k] + 1.0f; nrm += v * v; }
                float inv = __fdividef(1.0f, nrm);
                #pragma unroll
                for (int k = 0; k < 9; ++k) Z[k] *= inv;
                float iso, a2[3], s2[5];
                decomp9(Z, &iso, a2, s2);
                cpn[0 * PLANE + c] = a2[0];
                cpn[1 * PLANE + c] = a2[1];
                cpn[2 * PLANE + c] = a2[2];
                cpn[3 * PLANE + c] = s2[0];
                cpn[4 * PLANE + c] = s2[1];
                cpn[5 * PLANE + c] = s2[2];
                cpn[6 * PLANE + c] = s2[3];
                cpn[7 * PLANE + c] = s2[4];
                cpn[8 * PLANE + c] = iso;
            }
        }
        __syncwarp();

        // ---- post mixes ----
        {
            unsigned long long accA[3][2][4] = {};
            sector_pass<3>(smWA_b, cp, lane, accA);
            #pragma unroll
            for (int k = 0; k < 3; ++k)
                #pragma unroll
                for (int h = 0; h < 2; ++h)
                    #pragma unroll
                    for (int n = 0; n < 4; ++n) ya[k][h][n] = sum2(accA[k][h][n]);
        }
        {
            unsigned long long accS[5][2][4] = {};
            sector_pass<5>(smWS_b, cp + 3 * PLANE, lane, accS);
            #pragma unroll
            for (int k = 0; k < 5; ++k)
                #pragma unroll
                for (int h = 0; h < 2; ++h)
                    #pragma unroll
                    for (int n = 0; n < 4; ++n) ys[k][h][n] = sum2(accS[k][h][n]);
        }
        {
            unsigned long long accI[1][2][4] = {};
            sector_pass<1>(smWI_b, cp + 8 * PLANE, lane, accI);
            #pragma unroll
            for (int h = 0; h < 2; ++h)
                #pragma unroll
                for (int n = 0; n < 4; ++n) yi[h][n] = sum2(accI[0][h][n]);
        }
        __syncwarp();

        // ---- output: O = Y2 + Y2@Y2, stage per node, store coalesced ----
        #pragma unroll
        for (int n = 0; n < 4; ++n) {
            int node = n0 + n;
            #pragma unroll
            for (int h = 0; h < 2; ++h) {
                int c = lane + 32 * h;
                float av[3] = {ya[0][h][n], ya[1][h][n], ya[2][h][n]};
                float sv[5] = {ys[0][h][n], ys[1][h][n], ys[2][h][n],
                               ys[3][h][n], ys[4][h][n]};
                float Y2[9];
                build9(yi[h][n], av, sv, Y2);
                float* od = xs + c * 9;
                #pragma unroll
                for (int i = 0; i < 3; ++i)
                    #pragma unroll
                    for (int jj = 0; jj < 3; ++jj) {
                        float acc = Y2[i * 3 + jj];
                        #pragma unroll
                        for (int k = 0; k < 3; ++k)
                            acc += Y2[i * 3 + k] * Y2[k * 3 + jj];
                        od[i * 3 + jj] = acc;
                    }
            }
            __syncwarp();
            if (node < N) {
                float4* dst = (float4*)(out + (size_t)node * 576);
                const float4* src = (const float4*)xs;
                #pragma unroll
                for (int i = 0; i < 5; ++i) {
                    int idx = lane + 32 * i;
                    if (idx < 144) dst[idx] = src[idx];
                }
            }
            __syncwarp();
        }
    }
}

// ---------------------------------------------------------------------------
extern "C" void kernel_launch(void* const* d_in, const int* in_sizes, int n_in,
                              void* d_out, int out_size)
{
    const float* X    = (const float*)d_in[0];
    const float* dist = (const float*)d_in[1];
    const int*   nb   = (const int*)d_in[2];
    const float* WIa  = (const float*)d_in[3];
    const float* WAa  = (const float*)d_in[4];
    const float* WSa  = (const float*)d_in[5];
    const float* WIb  = (const float*)d_in[6];
    const float* WAb  = (const float*)d_in[7];
    const float* WSb  = (const float*)d_in[8];
    const float* Wd   = (const float*)d_in[9];
    const float* bd   = (const float*)d_in[10];
    float* out = (float*)d_out;

    int N = in_sizes[0] / 576;
    int E = in_sizes[1];

    void* phi_ptr = nullptr;
    void* env_ptr = nullptr;
    cudaGetSymbolAddress(&phi_ptr, g_PHI);
    cudaGetSymbolAddress(&env_ptr, g_ENV);
    cudaMemsetAsync(phi_ptr, 0, sizeof(float) * (size_t)N * 32, 0);
    cudaMemsetAsync(env_ptr, 0, sizeof(float) * (size_t)N, 0);

    double e5    = exp(-5.0);
    double delta = (1.0 - e5) / 31.0;
    double bb    = (2.0 / 32.0) * (1.0 - e5);
    double beta  = 1.0 / (bb * bb);
    float  c2    = (float)(2.0 * beta * delta);
    float  qf    = (float)exp(-2.0 * beta * delta * delta);

    edge_kernel<<<(E + 255) / 256, 256>>>(dist, nb, E,
        (float)e5, (float)delta, (float)(1.0 / delta), (float)beta, c2, qf);

    static int smem_set = 0;
    if (!smem_set) {
        cudaFuncSetAttribute(node_kernel,
                             cudaFuncAttributeMaxDynamicSharedMemorySize,
                             SMEM_FLOATS * sizeof(float));
        smem_set = 1;
    }
    node_kernel<<<148, 256, SMEM_FLOATS * sizeof(float)>>>(
        X, WIa, WAa, WSa, WIb, WAb, WSb, Wd, bd, out, N);
}